// round 15
// baseline (speedup 1.0000x reference)
#include <cuda_runtime.h>
#include <math.h>

#define Bn 16
#define Cn 3
#define Hn 512
#define Wn 512
#define HW (Hn * Wn)           // 262144
#define CHW (Cn * HW)          // 786432
#define NTOT (Bn * Cn * HW)    // 12582912

#define RPB 16                 // owned rows per block
#define HR (RPB + 2)           // 18 smem rows
#define CW 256                 // owned cols per block (2 col-halves per image row)
#define SW 264                 // smem row width: gcols c0-4 .. c0+259
#define SVPR 66                // float4 groups per smem row
#define NITEMS (HR * SVPR)     // 1188
#define NTHREADS 256
#define NBLK (Bn * 32 * 2)     // 1024 (bid = b*64 + rb*2 + half)

// Per-block partials (RAW scale, deferred 1/255), each written exactly once.
__device__ float g_psum[NBLK];
__device__ float g_psq[NBLK];
__device__ float g_pS[NBLK];
__device__ unsigned int g_count;   // zero-init; last block resets to 0

__device__ __forceinline__ int reflect(int i, int n) {
    return (i < 0) ? -i : ((i >= n) ? 2 * n - 2 - i : i);
}
__device__ __forceinline__ float sgnsel(float rs, float re) {
    // sign bit set iff rs < re (mask); rs >= 0 always.
    return (rs < re) ? __int_as_float(__float_as_int(rs) | 0x80000000u) : rs;
}

__global__ __launch_bounds__(NTHREADS) void fused_kernel(
    const float* __restrict__ sr,
    const float* __restrict__ srema,
    const float* __restrict__ hr,
    float* __restrict__ out)
{
    __shared__ float rt[HR][SW];   // 18.6 KB; idx k = gcol (c0-4+k)

    const int tid  = threadIdx.x;
    const int bid  = blockIdx.x;
    const int half = bid & 1;
    const int rb   = (bid >> 1) & 31;
    const int b    = bid >> 6;
    const int h0   = rb * RPB;
    const int c0   = half * CW;
    const int base = b * CHW;
    // exactly one image-edge vector per row: left edge (half 0) or right (half 1)
    const int spec_v = half ? (SVPR - 1) : 0;

    // --- Phase 1: residuals for 18 rows x 264 cols (1KB contiguous segments) --
#pragma unroll
    for (int k = 0; k < 5; ++k) {
        const int t = tid + k * NTHREADS;
        if (k == 4 && t >= NITEMS) break;
        const int row = t / SVPR;
        const int v   = t - row * SVPR;
        const int gh  = reflect(h0 - 1 + row, Hn);
        const int rowbase = base + gh * Wn;
        float4 o4;
        if (v != spec_v) {
            const int ix = rowbase + (c0 - 4) + 4 * v;
            float4 h0v = __ldg((const float4*)(hr    + ix));
            float4 s0v = __ldg((const float4*)(sr    + ix));
            float4 e0v = __ldg((const float4*)(srema + ix));
            float4 h1v = __ldg((const float4*)(hr    + ix + HW));
            float4 s1v = __ldg((const float4*)(sr    + ix + HW));
            float4 e1v = __ldg((const float4*)(srema + ix + HW));
            float4 h2v = __ldg((const float4*)(hr    + ix + 2 * HW));
            float4 s2v = __ldg((const float4*)(sr    + ix + 2 * HW));
            float4 e2v = __ldg((const float4*)(srema + ix + 2 * HW));
            {
                float rs = fabsf(h0v.x-s0v.x) + fabsf(h1v.x-s1v.x) + fabsf(h2v.x-s2v.x);
                float re = fabsf(h0v.x-e0v.x) + fabsf(h1v.x-e1v.x) + fabsf(h2v.x-e2v.x);
                o4.x = sgnsel(rs, re);
            }
            {
                float rs = fabsf(h0v.y-s0v.y) + fabsf(h1v.y-s1v.y) + fabsf(h2v.y-s2v.y);
                float re = fabsf(h0v.y-e0v.y) + fabsf(h1v.y-e1v.y) + fabsf(h2v.y-e2v.y);
                o4.y = sgnsel(rs, re);
            }
            {
                float rs = fabsf(h0v.z-s0v.z) + fabsf(h1v.z-s1v.z) + fabsf(h2v.z-s2v.z);
                float re = fabsf(h0v.z-e0v.z) + fabsf(h1v.z-e1v.z) + fabsf(h2v.z-e2v.z);
                o4.z = sgnsel(rs, re);
            }
            {
                float rs = fabsf(h0v.w-s0v.w) + fabsf(h1v.w-s1v.w) + fabsf(h2v.w-s2v.w);
                float re = fabsf(h0v.w-e0v.w) + fabsf(h1v.w-e1v.w) + fabsf(h2v.w-e2v.w);
                o4.w = sgnsel(rs, re);
            }
        } else {
            // image-edge vector: per-element column reflect, scalar loads
            float vals[4];
            const int gw0 = (c0 - 4) + 4 * v;
#pragma unroll
            for (int e = 0; e < 4; ++e) {
                const int gw = reflect(gw0 + e, Wn);
                const int ix = rowbase + gw;
                float rs = 0.f, re = 0.f;
#pragma unroll
                for (int c = 0; c < Cn; ++c) {
                    float h  = __ldg(hr    + ix + c * HW);
                    float s  = __ldg(sr    + ix + c * HW);
                    float se = __ldg(srema + ix + c * HW);
                    rs += fabsf(h - s);
                    re += fabsf(h - se);
                }
                vals[e] = sgnsel(rs, re);
            }
            o4 = make_float4(vals[0], vals[1], vals[2], vals[3]);
        }
        *(float4*)(&rt[row][4 * v]) = o4;
    }
    __syncthreads();

    // --- Phase 2: branch-free 3x3 variance, 4 groups of 4 px per thread ------
    float lsum = 0.f, lsq = 0.f, lS = 0.f;
#pragma unroll
    for (int k = 0; k < 4; ++k) {
        const int g   = tid + k * NTHREADS;   // 0..1023
        const int r   = g >> 6;               // owned row 0..15
        const int cg  = g & 63;               // col group 0..63
        const int lc0 = (cg << 2) + 4;        // smem idx of owned col group

        float4 T = *(const float4*)(&rt[r    ][lc0]);
        float4 M = *(const float4*)(&rt[r + 1][lc0]);
        float4 D = *(const float4*)(&rt[r + 2][lc0]);

        float tl = rt[r    ][lc0 - 1], tr2 = rt[r    ][lc0 + 4];
        float ml = rt[r + 1][lc0 - 1], mr  = rt[r + 1][lc0 + 4];
        float dl = rt[r + 2][lc0 - 1], dr  = rt[r + 2][lc0 + 4];

        float A0[4], B0[4], A1[4], B1[4], A2[4], B2[4];
        {
            float pl = fabsf(tl), p0 = fabsf(T.x), p1 = fabsf(T.y),
                  p2 = fabsf(T.z), p3 = fabsf(T.w), pr = fabsf(tr2);
            A0[0]=pl+p0+p1; A0[1]=p0+p1+p2; A0[2]=p1+p2+p3; A0[3]=p2+p3+pr;
            B0[0]=pl*pl+p0*p0+p1*p1; B0[1]=p0*p0+p1*p1+p2*p2;
            B0[2]=p1*p1+p2*p2+p3*p3; B0[3]=p2*p2+p3*p3+pr*pr;
        }
        {
            float pl = fabsf(ml), p0 = fabsf(M.x), p1 = fabsf(M.y),
                  p2 = fabsf(M.z), p3 = fabsf(M.w), pr = fabsf(mr);
            A1[0]=pl+p0+p1; A1[1]=p0+p1+p2; A1[2]=p1+p2+p3; A1[3]=p2+p3+pr;
            B1[0]=pl*pl+p0*p0+p1*p1; B1[1]=p0*p0+p1*p1+p2*p2;
            B1[2]=p1*p1+p2*p2+p3*p3; B1[3]=p2*p2+p3*p3+pr*pr;
        }
        {
            float pl = fabsf(dl), p0 = fabsf(D.x), p1 = fabsf(D.y),
                  p2 = fabsf(D.z), p3 = fabsf(D.w), pr = fabsf(dr);
            A2[0]=pl+p0+p1; A2[1]=p0+p1+p2; A2[2]=p1+p2+p3; A2[3]=p2+p3+pr;
            B2[0]=pl*pl+p0*p0+p1*p1; B2[1]=p0*p0+p1*p1+p2*p2;
            B2[2]=p1*p1+p2*p2+p3*p3; B2[3]=p2*p2+p3*p3+pr*pr;
        }

        const float cen[4] = { M.x, M.y, M.z, M.w };
#pragma unroll
        for (int x = 0; x < 4; ++x) {
            float s  = A0[x] + A1[x] + A2[x];
            float sq = B0[x] + B1[x] + B2[x];
            float lv = (sq - s * s * (1.0f / 9.0f)) * (1.0f / 8.0f);
            float r4 = fabsf(cen[x]);
            lS   += signbit(cen[x]) ? 0.0f : fabsf(lv) * r4;
            lsum += r4;
            lsq  += r4 * r4;
        }
    }

    // --- Block reduction --------------------------------------------------------
    __shared__ float wsum[8], wsq[8], wS[8];
#pragma unroll
    for (int o = 16; o > 0; o >>= 1) {
        lsum += __shfl_down_sync(0xffffffffu, lsum, o);
        lsq  += __shfl_down_sync(0xffffffffu, lsq,  o);
        lS   += __shfl_down_sync(0xffffffffu, lS,   o);
    }
    const int warp = tid >> 5;
    const int lane = tid & 31;
    if (lane == 0) { wsum[warp] = lsum; wsq[warp] = lsq; wS[warp] = lS; }
    __syncthreads();

    __shared__ bool isLast;
    if (tid == 0) {
        float a = 0.f, c = 0.f, d = 0.f;
#pragma unroll
        for (int i = 0; i < 8; ++i) { a += wsum[i]; c += wsq[i]; d += wS[i]; }
        g_psum[bid] = a;
        g_psq[bid]  = c;
        g_pS[bid]   = d;
        __threadfence();
        unsigned prev = atomicAdd(&g_count, 1u);
        isLast = (prev == NBLK - 1);
    }
    __syncthreads();

    // --- Last block: per-batch patch weight + final loss -------------------------
    if (isLast) {
        if (tid == 0) g_count = 0;   // reset for next graph replay
        __shared__ float sres[Bn];
        // 8 warps x 2 batches; 64 partials per batch = 2 per lane.
#pragma unroll
        for (int j = 0; j < 2; ++j) {
            const int bb = warp * 2 + j;
            float s = 0.f, sq = 0.f, S = 0.f;
#pragma unroll
            for (int e = 0; e < 2; ++e) {
                const int idx = bb * 64 + lane * 2 + e;
                s  += __ldcg(&g_psum[idx]);
                sq += __ldcg(&g_psq[idx]);
                S  += __ldcg(&g_pS[idx]);
            }
#pragma unroll
            for (int o = 16; o > 0; o >>= 1) {
                s  += __shfl_down_sync(0xffffffffu, s,  o);
                sq += __shfl_down_sync(0xffffffffu, sq, o);
                S  += __shfl_down_sync(0xffffffffu, S,  o);
            }
            if (lane == 0) {
                const float n = (float)HW;
                float var = (sq - s * s / n) / (n - 1.0f);   // raw scale
                float w = (var > 0.0f) ? exp2f(0.2f * log2f(var)) : 0.0f;
                sres[bb] = w * S;
            }
        }
        __syncthreads();
        if (tid == 0) {
            float acc = 0.f;
#pragma unroll
            for (int i = 0; i < Bn; ++i) acc += sres[i];
            // loss = 255/NTOT * sum_b (k^2 var)^0.2 * k^3 S, k = 1/255
            //      = 255^(-2.4)/NTOT * sum_b var_raw^0.2 * S_raw
            double Kd = pow(255.0, -2.4) / (double)NTOT;
            out[0] = (float)((double)acc * Kd);
        }
    }
}

// ---------------------------------------------------------------------------
extern "C" void kernel_launch(void* const* d_in, const int* in_sizes, int n_in,
                              void* d_out, int out_size) {
    const float* sr    = (const float*)d_in[0];
    const float* srema = (const float*)d_in[1];
    const float* hr    = (const float*)d_in[2];
    float* out = (float*)d_out;

    fused_kernel<<<NBLK, NTHREADS>>>(sr, srema, hr, out);
}

// round 17
// speedup vs baseline: 1.0533x; 1.0533x over previous
#include <cuda_runtime.h>
#include <math.h>

#define Bn 16
#define Cn 3
#define Hn 512
#define Wn 512
#define HW (Hn * Wn)           // 262144
#define CHW (Cn * HW)          // 786432
#define NTOT (Bn * Cn * HW)    // 12582912

#define RPB 16                 // owned image rows per block
#define HR (RPB + 2)           // 18 smem rows
#define NTHREADS 256           // warps 0-3 load, 4-7 stencil
#define RBLK (Hn / RPB)        // 32
#define NBLK (RBLK * Bn)       // 512

__device__ float g_psum[NBLK];
__device__ float g_psq[NBLK];
__device__ float g_pS[NBLK];
__device__ unsigned int g_count;   // zero-init; last block resets to 0

__device__ __forceinline__ int reflect(int i, int n) {
    return (i < 0) ? -i : ((i >= n) ? 2 * n - 2 - i : i);
}
__device__ __forceinline__ float sgnsel(float rs, float re) {
    return (rs < re) ? __int_as_float(__float_as_int(rs) | 0x80000000u) : rs;
}
__device__ __forceinline__ void bar_arrive(int id) {
    asm volatile("bar.arrive %0, %1;" :: "r"(id), "r"(NTHREADS));
}
__device__ __forceinline__ void bar_wait(int id) {
    asm volatile("bar.sync %0, %1;" :: "r"(id), "r"(NTHREADS) : "memory");
}

__global__ __launch_bounds__(NTHREADS) void fused_kernel(
    const float* __restrict__ sr,
    const float* __restrict__ srema,
    const float* __restrict__ hr,
    float* __restrict__ out)
{
    __shared__ float rt[HR][Wn];   // 36 KB signed raw residuals, full-width rows

    const int tid  = threadIdx.x;
    const int warp = tid >> 5;
    const int lane = tid & 31;
    const int bid  = blockIdx.x;
    const int b    = bid >> 5;
    const int rb   = bid & 31;
    const int h0   = rb * RPB;
    const int base = b * CHW;

    float lsum = 0.f, lsq = 0.f, lS = 0.f;

    if (warp < 4) {
        // ===== PRODUCER: 4 warps stream 9 bands of 2 rows.
        // Protocol: after band >= 1 is written, arrive(band).
        // Barrier id k complete  <=>  smem rows 0 .. 2k+1 are valid.
        const int lt = tid;   // 0..127
#pragma unroll
        for (int band = 0; band < 9; ++band) {
#pragma unroll
            for (int i = 0; i < 2; ++i) {
                const int item = lt + i * 128;        // 0..255
                const int row  = 2 * band + (item >> 7);
                const int v    = item & 127;
                const int gh   = reflect(h0 - 1 + row, Hn);
                const int ix   = base + gh * Wn + 4 * v;

                float4 h0v = __ldg((const float4*)(hr    + ix));
                float4 s0v = __ldg((const float4*)(sr    + ix));
                float4 e0v = __ldg((const float4*)(srema + ix));
                float4 h1v = __ldg((const float4*)(hr    + ix + HW));
                float4 s1v = __ldg((const float4*)(sr    + ix + HW));
                float4 e1v = __ldg((const float4*)(srema + ix + HW));
                float4 h2v = __ldg((const float4*)(hr    + ix + 2 * HW));
                float4 s2v = __ldg((const float4*)(sr    + ix + 2 * HW));
                float4 e2v = __ldg((const float4*)(srema + ix + 2 * HW));

                float4 o4;
                {
                    float rs = fabsf(h0v.x-s0v.x) + fabsf(h1v.x-s1v.x) + fabsf(h2v.x-s2v.x);
                    float re = fabsf(h0v.x-e0v.x) + fabsf(h1v.x-e1v.x) + fabsf(h2v.x-e2v.x);
                    o4.x = sgnsel(rs, re);
                }
                {
                    float rs = fabsf(h0v.y-s0v.y) + fabsf(h1v.y-s1v.y) + fabsf(h2v.y-s2v.y);
                    float re = fabsf(h0v.y-e0v.y) + fabsf(h1v.y-e1v.y) + fabsf(h2v.y-e2v.y);
                    o4.y = sgnsel(rs, re);
                }
                {
                    float rs = fabsf(h0v.z-s0v.z) + fabsf(h1v.z-s1v.z) + fabsf(h2v.z-s2v.z);
                    float re = fabsf(h0v.z-e0v.z) + fabsf(h1v.z-e1v.z) + fabsf(h2v.z-e2v.z);
                    o4.z = sgnsel(rs, re);
                }
                {
                    float rs = fabsf(h0v.w-s0v.w) + fabsf(h1v.w-s1v.w) + fabsf(h2v.w-s2v.w);
                    float re = fabsf(h0v.w-e0v.w) + fabsf(h1v.w-e1v.w) + fabsf(h2v.w-e2v.w);
                    o4.w = sgnsel(rs, re);
                }
                *(float4*)(&rt[row][4 * v]) = o4;
            }
            if (band >= 1) {
                __threadfence_block();    // order STS before arrive
                bar_arrive(band);         // non-blocking: keep streaming
            }
        }
    } else {
        // ===== CONSUMER: 4 warps. Step j computes owned rows 2j, 2j+1,
        // reading smem rows 2j .. 2j+3  ->  wait barrier id j+1.
        const int st = tid - 128;   // 0..127
#pragma unroll
        for (int j = 0; j < 8; ++j) {
            bar_wait(j + 1);
#pragma unroll
            for (int i = 0; i < 2; ++i) {
                const int item = st + i * 128;          // 0..255
                const int r    = 2 * j + (item >> 7);   // owned row
                const int cg   = item & 127;
                const int c0   = cg << 2;

                float4 T = *(const float4*)(&rt[r    ][c0]);
                float4 M = *(const float4*)(&rt[r + 1][c0]);
                float4 D = *(const float4*)(&rt[r + 2][c0]);

                const int lc = (cg == 0)   ? 1   : c0 - 1;
                const int rc = (cg == 127) ? 510 : c0 + 4;
                float tl = rt[r    ][lc], tr2 = rt[r    ][rc];
                float ml = rt[r + 1][lc], mr  = rt[r + 1][rc];
                float dl = rt[r + 2][lc], dr  = rt[r + 2][rc];

                float A0[4], B0[4], A1[4], B1[4], A2[4], B2[4];
                {
                    float pl = fabsf(tl), p0 = fabsf(T.x), p1 = fabsf(T.y),
                          p2 = fabsf(T.z), p3 = fabsf(T.w), pr = fabsf(tr2);
                    A0[0]=pl+p0+p1; A0[1]=p0+p1+p2; A0[2]=p1+p2+p3; A0[3]=p2+p3+pr;
                    B0[0]=pl*pl+p0*p0+p1*p1; B0[1]=p0*p0+p1*p1+p2*p2;
                    B0[2]=p1*p1+p2*p2+p3*p3; B0[3]=p2*p2+p3*p3+pr*pr;
                }
                {
                    float pl = fabsf(ml), p0 = fabsf(M.x), p1 = fabsf(M.y),
                          p2 = fabsf(M.z), p3 = fabsf(M.w), pr = fabsf(mr);
                    A1[0]=pl+p0+p1; A1[1]=p0+p1+p2; A1[2]=p1+p2+p3; A1[3]=p2+p3+pr;
                    B1[0]=pl*pl+p0*p0+p1*p1; B1[1]=p0*p0+p1*p1+p2*p2;
                    B1[2]=p1*p1+p2*p2+p3*p3; B1[3]=p2*p2+p3*p3+pr*pr;
                }
                {
                    float pl = fabsf(dl), p0 = fabsf(D.x), p1 = fabsf(D.y),
                          p2 = fabsf(D.z), p3 = fabsf(D.w), pr = fabsf(dr);
                    A2[0]=pl+p0+p1; A2[1]=p0+p1+p2; A2[2]=p1+p2+p3; A2[3]=p2+p3+pr;
                    B2[0]=pl*pl+p0*p0+p1*p1; B2[1]=p0*p0+p1*p1+p2*p2;
                    B2[2]=p1*p1+p2*p2+p3*p3; B2[3]=p2*p2+p3*p3+pr*pr;
                }

                const float cen[4] = { M.x, M.y, M.z, M.w };
#pragma unroll
                for (int x = 0; x < 4; ++x) {
                    float s  = A0[x] + A1[x] + A2[x];
                    float sq = B0[x] + B1[x] + B2[x];
                    float lv = (sq - s * s * (1.0f / 9.0f)) * (1.0f / 8.0f);
                    float r4 = fabsf(cen[x]);
                    lS   += signbit(cen[x]) ? 0.0f : fabsf(lv) * r4;
                    lsum += r4;
                    lsq  += r4 * r4;
                }
            }
        }
    }

    // --- Block reduction (loader warps contribute zeros) ----------------------
    __shared__ float wsum[8], wsq[8], wS[8];
#pragma unroll
    for (int o = 16; o > 0; o >>= 1) {
        lsum += __shfl_down_sync(0xffffffffu, lsum, o);
        lsq  += __shfl_down_sync(0xffffffffu, lsq,  o);
        lS   += __shfl_down_sync(0xffffffffu, lS,   o);
    }
    if (lane == 0) { wsum[warp] = lsum; wsq[warp] = lsq; wS[warp] = lS; }
    __syncthreads();

    __shared__ bool isLast;
    if (tid == 0) {
        float a = 0.f, c = 0.f, d = 0.f;
#pragma unroll
        for (int i = 0; i < 8; ++i) { a += wsum[i]; c += wsq[i]; d += wS[i]; }
        g_psum[bid] = a;
        g_psq[bid]  = c;
        g_pS[bid]   = d;
        __threadfence();
        unsigned prev = atomicAdd(&g_count, 1u);
        isLast = (prev == NBLK - 1);
    }
    __syncthreads();

    // --- Last block: per-batch patch weight + final loss -----------------------
    if (isLast) {
        if (tid == 0) g_count = 0;   // reset for next graph replay
        __shared__ float sres[Bn];
        // 8 warps x 2 batches; 32 partials per batch (1 per lane).
#pragma unroll
        for (int j = 0; j < 2; ++j) {
            const int bb  = warp * 2 + j;
            const int idx = bb * 32 + lane;
            float s  = __ldcg(&g_psum[idx]);
            float sq = __ldcg(&g_psq[idx]);
            float S  = __ldcg(&g_pS[idx]);
#pragma unroll
            for (int o = 16; o > 0; o >>= 1) {
                s  += __shfl_down_sync(0xffffffffu, s,  o);
                sq += __shfl_down_sync(0xffffffffu, sq, o);
                S  += __shfl_down_sync(0xffffffffu, S,  o);
            }
            if (lane == 0) {
                const float n = (float)HW;
                float var = (sq - s * s / n) / (n - 1.0f);   // raw scale
                float w = (var > 0.0f) ? exp2f(0.2f * log2f(var)) : 0.0f;
                sres[bb] = w * S;
            }
        }
        __syncthreads();
        if (tid == 0) {
            float acc = 0.f;
#pragma unroll
            for (int i = 0; i < Bn; ++i) acc += sres[i];
            // loss = 255^(-2.4)/NTOT * sum_b var_raw^0.2 * S_raw
            double Kd = pow(255.0, -2.4) / (double)NTOT;
            out[0] = (float)((double)acc * Kd);
        }
    }
}

// ---------------------------------------------------------------------------
extern "C" void kernel_launch(void* const* d_in, const int* in_sizes, int n_in,
                              void* d_out, int out_size) {
    const float* sr    = (const float*)d_in[0];
    const float* srema = (const float*)d_in[1];
    const float* hr    = (const float*)d_in[2];
    float* out = (float*)d_out;

    fused_kernel<<<NBLK, NTHREADS>>>(sr, srema, hr, out);
}